// round 14
// baseline (speedup 1.0000x reference)
#include <cuda_runtime.h>
#include <cuda_bf16.h>
#include <stdint.h>

#define Qlen 2048
#define Slen 2048
#define Dd   64
#define BHn  32
#define NT   16
#define QS   (Qlen * Slen)
#define NROWS (BHn * Qlen)

// ---------------- device scratch (static, allowed) ----------------
__device__ __align__(16) __nv_bfloat16 g_qh[(size_t)BHn * Qlen * Dd];
__device__ __align__(16) __nv_bfloat16 g_ql[(size_t)BHn * Qlen * Dd];
__device__ __align__(16) __nv_bfloat16 g_kth[(size_t)BHn * Slen * Dd];  // k^T: [bh][s][d]
__device__ __align__(16) __nv_bfloat16 g_ktl[(size_t)BHn * Slen * Dd];
__device__ __align__(16) __nv_bfloat16 g_vth[(size_t)BHn * Dd * Slen];  // v^T: [bh][d][s]
__device__ __align__(16) __nv_bfloat16 g_vtl[(size_t)BHn * Dd * Slen];
__device__ float g_partial[(size_t)NROWS * NT];

// ---------------- warp MMA helpers (baseline PTX, sm_80+) ----------------
__device__ __forceinline__ uint32_t smem_u32(const void* p) {
    uint32_t a;
    asm("{ .reg .u64 t; cvta.to.shared.u64 t, %1; cvt.u32.u64 %0, t; }" : "=r"(a) : "l"(p));
    return a;
}
__device__ __forceinline__ void ldsm4(uint32_t (&r)[4], uint32_t addr) {
    asm volatile("ldmatrix.sync.aligned.m8n8.x4.shared.b16 {%0,%1,%2,%3}, [%4];"
        : "=r"(r[0]), "=r"(r[1]), "=r"(r[2]), "=r"(r[3]) : "r"(addr));
}
__device__ __forceinline__ void mma_bf16(float (&d)[4], const uint32_t (&a)[4],
                                         uint32_t b0, uint32_t b1) {
    asm volatile("mma.sync.aligned.m16n8k16.row.col.f32.bf16.bf16.f32 "
        "{%0,%1,%2,%3}, {%4,%5,%6,%7}, {%8,%9}, {%0,%1,%2,%3};"
        : "+f"(d[0]), "+f"(d[1]), "+f"(d[2]), "+f"(d[3])
        : "r"(a[0]), "r"(a[1]), "r"(a[2]), "r"(a[3]), "r"(b0), "r"(b1));
}
__device__ __forceinline__ void split4(float4 x, uint2& hi, uint2& lo) {
    __nv_bfloat16 h0 = __float2bfloat16_rn(x.x), h1 = __float2bfloat16_rn(x.y);
    __nv_bfloat16 h2 = __float2bfloat16_rn(x.z), h3 = __float2bfloat16_rn(x.w);
    float r0 = x.x - __bfloat162float(h0), r1 = x.y - __bfloat162float(h1);
    float r2 = x.z - __bfloat162float(h2), r3 = x.w - __bfloat162float(h3);
    __nv_bfloat162 a = {h0, h1}, b = {h2, h3};
    __nv_bfloat162 c = {__float2bfloat16_rn(r0), __float2bfloat16_rn(r1)};
    __nv_bfloat162 d = {__float2bfloat16_rn(r2), __float2bfloat16_rn(r3)};
    hi.x = *(uint32_t*)&a;  hi.y = *(uint32_t*)&b;
    lo.x = *(uint32_t*)&c;  lo.y = *(uint32_t*)&d;
}

#define SPB 144   // smem row stride in bytes for bf16 tiles (64 elems + 8 pad)
#define NINF __int_as_float(0xff800000)
#define NEG9 (-1.0e9f)

// ---------------- k0: conversions / transposes ----------------
__global__ __launch_bounds__(256) void k0_q(const float* __restrict__ Q) {
    int j = blockIdx.x * 256 + threadIdx.x;
    float4 x = ((const float4*)Q)[j];
    uint2 hi, lo; split4(x, hi, lo);
    ((uint2*)g_qh)[j] = hi;  ((uint2*)g_ql)[j] = lo;
}
__global__ __launch_bounds__(256) void k0_k(const float* __restrict__ K) {
    __shared__ float T[64][65];
    const int tid = threadIdx.x, bh = blockIdx.y, s0 = blockIdx.x * 64;
    const int r = tid >> 4, c4 = tid & 15;
    #pragma unroll
    for (int i = 0; i < 4; ++i) {
        int d = r + i * 16;
        float4 x = *(const float4*)(K + ((size_t)(bh * Dd + d)) * Slen + s0 + c4 * 4);
        T[d][c4 * 4] = x.x; T[d][c4 * 4 + 1] = x.y; T[d][c4 * 4 + 2] = x.z; T[d][c4 * 4 + 3] = x.w;
    }
    __syncthreads();
    #pragma unroll
    for (int i = 0; i < 4; ++i) {
        int s = r + i * 16;
        float4 x = make_float4(T[c4 * 4][s], T[c4 * 4 + 1][s], T[c4 * 4 + 2][s], T[c4 * 4 + 3][s]);
        uint2 hi, lo; split4(x, hi, lo);
        size_t off = ((size_t)(bh * Slen + s0 + s)) * Dd + c4 * 4;
        ((uint2*)g_kth)[off >> 2] = hi;  ((uint2*)g_ktl)[off >> 2] = lo;
    }
}
__global__ __launch_bounds__(256) void k0_v(const float* __restrict__ V) {
    __shared__ float T[64][65];
    const int tid = threadIdx.x, bh = blockIdx.y, s0 = blockIdx.x * 64;
    const int r = tid >> 4, c4 = tid & 15;
    #pragma unroll
    for (int i = 0; i < 4; ++i) {
        int s = r + i * 16;
        float4 x = *(const float4*)(V + ((size_t)(bh * Slen + s0 + s)) * Dd + c4 * 4);
        T[s][c4 * 4] = x.x; T[s][c4 * 4 + 1] = x.y; T[s][c4 * 4 + 2] = x.z; T[s][c4 * 4 + 3] = x.w;
    }
    __syncthreads();
    #pragma unroll
    for (int i = 0; i < 4; ++i) {
        int d = r + i * 16;
        float4 x = make_float4(T[c4 * 4][d], T[c4 * 4 + 1][d], T[c4 * 4 + 2][d], T[c4 * 4 + 3][d]);
        uint2 hi, lo; split4(x, hi, lo);
        size_t off = ((size_t)(bh * Dd + d)) * Slen + s0 + c4 * 4;
        ((uint2*)g_vth)[off >> 2] = hi;  ((uint2*)g_vtl)[off >> 2] = lo;
    }
}

// ---------------- k1: 64x128 tile, causal-aware, 3 CTAs/SM ------------------
// Fill tiles also zero the attn output (absorbs k3's zero-fill into k1 slack).
// smem bytes: Qh@0 (64x144=9216), Ql@9216, Kh@18432 (128x144=18432), Kl@36864.
// Dst (float, 64 x 132 = 33792 B) aliased at 0 after MMA. Total 55296.
#define K1_SMEM 55296
__global__ __launch_bounds__(256, 3) void k1_scores(
    const float* __restrict__ Pp, const float* __restrict__ Mp,
    const unsigned char* __restrict__ KPM, const float* __restrict__ Sc,
    float* __restrict__ OutS, float* __restrict__ OutA)
{
    extern __shared__ char smem[];
    const uint32_t sb = smem_u32(smem);
    float* Dst = (float*)smem;
    const int tid = threadIdx.x, wid = tid >> 5, lane = tid & 31;
    const int bh = blockIdx.z, q0 = blockIdx.y * 64, s0 = blockIdx.x * 128, b = bh >> 4;

    // ---- fully-masked tile (s > q everywhere): scores = -1e9, attn = 0 ----
    if (s0 >= q0 + 64) {
        const float4 neg = make_float4(NEG9, NEG9, NEG9, NEG9);
        const float4 zer = make_float4(0.f, 0.f, 0.f, 0.f);
        const size_t base = (size_t)bh * QS + (size_t)q0 * Slen + s0;
        #pragma unroll
        for (int i = 0; i < 8; ++i) {
            int j = tid + i * 256;               // 2048 float4 = 64 rows x 32
            int row = j >> 5, c = j & 31;
            size_t off = base + (size_t)row * Slen + c * 4;
            __stcs((float4*)(OutS + off), neg);
            __stcs((float4*)(OutA + off), zer);
        }
        if (tid < 64)
            g_partial[((size_t)(bh * Qlen + q0 + tid)) * NT + blockIdx.x] = 0.f;
        return;
    }
    const bool needMask = (s0 + 127 > q0);       // any masked element in tile?
    const float scale = *Sc;

    // stage operands: Q 64 rows, K 128 rows (each 128B/row at stride 144B)
    {
        const uint4* qh = (const uint4*)(g_qh + ((size_t)(bh * Qlen + q0)) * Dd);
        const uint4* ql = (const uint4*)(g_ql + ((size_t)(bh * Qlen + q0)) * Dd);
        #pragma unroll
        for (int i = 0; i < 2; ++i) {
            int j = tid + i * 256;
            int r = j >> 3, c = j & 7;
            uint32_t so = r * SPB + c * 16;
            *(uint4*)(smem + so)        = qh[j];
            *(uint4*)(smem + 9216 + so) = ql[j];
        }
        const uint4* kh = (const uint4*)(g_kth + ((size_t)(bh * Slen + s0)) * Dd);
        const uint4* kl = (const uint4*)(g_ktl + ((size_t)(bh * Slen + s0)) * Dd);
        #pragma unroll
        for (int i = 0; i < 4; ++i) {
            int j = tid + i * 256;
            int r = j >> 3, c = j & 7;
            uint32_t so = r * SPB + c * 16;
            *(uint4*)(smem + 18432 + so) = kh[j];
            *(uint4*)(smem + 36864 + so) = kl[j];
        }
    }
    __syncthreads();

    const int warp_m0 = (wid & 3) * 16;
    const int warp_n0 = (wid >> 2) * 64;
    const int quad = lane >> 3, rq = lane & 7;
    const int a_row = ((quad & 1) << 3) + rq;
    const int a_colb = ((quad >> 1) << 4);
    const int b_nfl = quad >> 1;
    const int b_kofb = ((quad & 1) << 4);

    float acc[8][4] = {};
    #pragma unroll
    for (int ks = 0; ks < 4; ++ks) {
        uint32_t ah[4], al[4];
        {
            uint32_t off = (uint32_t)(warp_m0 + a_row) * SPB + ks * 32 + a_colb;
            ldsm4(ah, sb + off);
            ldsm4(al, sb + 9216 + off);
        }
        #pragma unroll
        for (int p = 0; p < 4; ++p) {
            uint32_t off = (uint32_t)(warp_n0 + (p * 2 + b_nfl) * 8 + rq) * SPB + ks * 32 + b_kofb;
            uint32_t th[4], tl[4];
            ldsm4(th, sb + 18432 + off);
            ldsm4(tl, sb + 36864 + off);
            mma_bf16(acc[p * 2],     ah, th[0], th[1]);
            mma_bf16(acc[p * 2],     al, th[0], th[1]);
            mma_bf16(acc[p * 2],     ah, tl[0], tl[1]);
            mma_bf16(acc[p * 2 + 1], ah, th[2], th[3]);
            mma_bf16(acc[p * 2 + 1], al, th[2], th[3]);
            mma_bf16(acc[p * 2 + 1], ah, tl[2], tl[3]);
        }
    }
    __syncthreads();   // operands dead; alias Dst over them

    // acc -> smem stage (stride 132 floats => float4-aligned reads)
    {
        const int g = lane >> 2, t2 = (lane & 3) * 2;
        #pragma unroll
        for (int nf = 0; nf < 8; ++nf) {
            int row = warp_m0 + g;
            int col = warp_n0 + nf * 8 + t2;
            *(float2*)&Dst[row * 132 + col]       = make_float2(acc[nf][0], acc[nf][1]);
            *(float2*)&Dst[(row + 8) * 132 + col] = make_float2(acc[nf][2], acc[nf][3]);
        }
    }
    __syncthreads();

    // epilogue: 8 rows per warp in 2 batches of 4; batched loads for MLP
    {
        const uchar4 kp = *(const uchar4*)(KPM + b * Slen + s0 + lane * 4);
        #pragma unroll
        for (int half = 0; half < 2; ++half) {
            float4 pv[4], mv[4];
            #pragma unroll
            for (int it = 0; it < 4; ++it) {
                int qg = q0 + wid * 8 + half * 4 + it;
                pv[it] = __ldcs((const float4*)(Pp + (size_t)bh * QS + (size_t)qg * Slen + s0 + lane * 4));
                if (needMask)
                    mv[it] = *(const float4*)(Mp + (size_t)qg * Slen + s0 + lane * 4);
                else
                    mv[it] = make_float4(0.f, 0.f, 0.f, 0.f);
            }
            #pragma unroll
            for (int it = 0; it < 4; ++it) {
                int qr = wid * 8 + half * 4 + it, qg = q0 + qr;
                float4 dv = *(const float4*)(Dst + qr * 132 + lane * 4);
                float4 r;
                r.x = fmaf(dv.x, scale, pv[it].x) + mv[it].x;
                r.y = fmaf(dv.y, scale, pv[it].y) + mv[it].y;
                r.z = fmaf(dv.z, scale, pv[it].z) + mv[it].z;
                r.w = fmaf(dv.w, scale, pv[it].w) + mv[it].w;
                if (kp.x) r.x = NINF;
                if (kp.y) r.y = NINF;
                if (kp.z) r.z = NINF;
                if (kp.w) r.w = NINF;
                __stcs((float4*)(OutS + (size_t)bh * QS + (size_t)qg * Slen + s0 + lane * 4), r);
                float e = __expf(r.x) + __expf(r.y) + __expf(r.z) + __expf(r.w);
                #pragma unroll
                for (int o = 16; o; o >>= 1) e += __shfl_xor_sync(0xffffffffu, e, o);
                if (lane == 0) g_partial[((size_t)(bh * Qlen + qg)) * NT + blockIdx.x] = e;
            }
        }
    }
}

// ---------------- k3: double-buffered attn write + out = attn @ v -----------
// Inlines the rowsum reduce (k2 eliminated). One __syncthreads per chunk.
// smem bytes: buf0 { Ah@0 (18432), Al@18432, Bh@36864 (9216), Bl@46080 }
//             buf1 { Ah@55296, Al@73728, Bh@92160, Bl@101376 }
//             inv@110592 (512).  Total 111104.  Dst (128x66 f32) aliases @0.
#define K3_SMEM 111104
__global__ __launch_bounds__(256, 2) void k3_out(
    const float* __restrict__ S, float* __restrict__ A, float* __restrict__ O)
{
    extern __shared__ char smem[];
    const uint32_t sb = smem_u32(smem);
    float* smInv = (float*)(smem + 110592);
    float* Dst = (float*)smem;
    const int tid = threadIdx.x, wid = tid >> 5, lane = tid & 31;
    const int bh = blockIdx.y, q0 = blockIdx.x * 128;
    const int cmax = min(32, 2 * (int)blockIdx.x + 2);   // chunks with any s <= q

    // inline rowsum reduce (replaces k2)
    if (tid < 128) {
        const float4* p = (const float4*)(g_partial + (size_t)(bh * Qlen + q0 + tid) * NT);
        float4 a = p[0], b = p[1], c = p[2], d = p[3];
        float s = a.x + a.y + a.z + a.w + b.x + b.y + b.z + b.w
                + c.x + c.y + c.z + c.w + d.x + d.y + d.z + d.w;
        smInv[tid] = 1.0f / s;
    }
    __syncthreads();

    const size_t sbase = (size_t)bh * QS + (size_t)q0 * Slen;
    const uint4* vh = (const uint4*)(g_vth + (size_t)bh * Dd * Slen);
    const uint4* vl = (const uint4*)(g_vtl + (size_t)bh * Dd * Slen);

    const int warp_m0 = (wid & 1) * 64;
    const int warp_n0 = (wid >> 1) * 16;
    const int quad = lane >> 3, rq = lane & 7;
    const int a_row = ((quad & 1) << 3) + rq;
    const int a_colb = ((quad >> 1) << 4);
    const int b_nfl = quad >> 1;
    const int b_kofb = ((quad & 1) << 4);

    const int sqr = tid >> 4, sf4 = tid & 15;
    const int vd  = tid >> 3, vc8 = tid & 7;

    float acc[4][2][4] = {};
    float4 xr[8];
    uint4  vb[2][2];

    // load chunk c into registers
    auto loadC = [&](int c) {
        #pragma unroll
        for (int i = 0; i < 8; ++i)
            xr[i] = __ldcs((const float4*)(S + sbase + (size_t)(sqr + i * 16) * Slen + c * 64 + sf4 * 4));
        #pragma unroll
        for (int i = 0; i < 2; ++i) {
            size_t eidx = (((size_t)(vd + i * 32) * Slen + c * 64) >> 3) + vc8;
            vb[i][0] = vh[eidx];  vb[i][1] = vl[eidx];
        }
    };
    // stage chunk c (regs) -> buffer (c&1): exp, attn store, smem split stores
    auto stageC = [&](int c) {
        const uint32_t A0 = (c & 1) * 55296u, A1 = A0 + 18432u;
        const uint32_t B0 = A0 + 36864u,      B1 = A0 + 46080u;
        #pragma unroll
        for (int i = 0; i < 8; ++i) {
            int qr = sqr + i * 16;
            float iv = smInv[qr];
            float4 p;
            p.x = __expf(xr[i].x) * iv;  p.y = __expf(xr[i].y) * iv;
            p.z = __expf(xr[i].z) * iv;  p.w = __expf(xr[i].w) * iv;
            __stcs((float4*)(A + sbase + (size_t)qr * Slen + c * 64 + sf4 * 4), p);
            uint2 hi, lo; split4(p, hi, lo);
            uint32_t so = (uint32_t)qr * SPB + sf4 * 8;
            *(uint2*)(smem + A0 + so) = hi;
            *(uint2*)(smem + A1 + so) = lo;
        }
        #pragma unroll
        for (int i = 0; i < 2; ++i) {
            uint32_t so = (uint32_t)(vd + i * 32) * SPB + vc8 * 16;
            *(uint4*)(smem + B0 + so) = vb[i][0];
            *(uint4*)(smem + B1 + so) = vb[i][1];
        }
    };

    loadC(0);
    stageC(0);
    __syncthreads();

    for (int c = 0; c < cmax; ++c) {
        if (c + 1 < cmax) loadC(c + 1);          // overlaps MMA below

        const uint32_t A0 = (c & 1) * 55296u, A1 = A0 + 18432u;
        const uint32_t B0 = A0 + 36864u,      B1 = A0 + 46080u;
        #pragma unroll
        for (int ks = 0; ks < 4; ++ks) {
            uint32_t bhf[4], blf[4];
            {
                uint32_t off = (uint32_t)(warp_n0 + b_nfl * 8 + rq) * SPB + ks * 32 + b_kofb;
                ldsm4(bhf, sb + B0 + off);
                ldsm4(blf, sb + B1 + off);
            }
            #pragma unroll
            for (int mf = 0; mf < 4; ++mf) {
                uint32_t ah[4], al[4];
                uint32_t off = (uint32_t)(warp_m0 + mf * 16 + a_row) * SPB + ks * 32 + a_colb;
                ldsm4(ah, sb + A0 + off);
                ldsm4(al, sb + A1 + off);
                mma_bf16(acc[mf][0], ah, bhf[0], bhf[1]);
                mma_bf16(acc[mf][0], al, bhf[0], bhf[1]);
                mma_bf16(acc[mf][0], ah, blf[0], blf[1]);
                mma_bf16(acc[mf][1], ah, bhf[2], bhf[3]);
                mma_bf16(acc[mf][1], al, bhf[2], bhf[3]);
                mma_bf16(acc[mf][1], ah, blf[2], blf[3]);
            }
        }
        if (c + 1 < cmax) stageC(c + 1);         // other buffer: no race with MMA
        __syncthreads();
    }

    // acc -> smem (stride 66) -> coalesced O write
    {
        const int g = lane >> 2, t2 = (lane & 3) * 2;
        #pragma unroll
        for (int mf = 0; mf < 4; ++mf)
            #pragma unroll
            for (int nf = 0; nf < 2; ++nf) {
                int row = warp_m0 + mf * 16 + g;
                int col = warp_n0 + nf * 8 + t2;
                *(float2*)&Dst[row * 66 + col]       = make_float2(acc[mf][nf][0], acc[mf][nf][1]);
                *(float2*)&Dst[(row + 8) * 66 + col] = make_float2(acc[mf][nf][2], acc[mf][nf][3]);
            }
    }
    __syncthreads();
    #pragma unroll
    for (int it = 0; it < 16; ++it) {
        int qr = wid * 16 + it;
        float2 o = *(const float2*)(Dst + qr * 66 + lane * 2);
        *(float2*)(O + ((size_t)(bh * Qlen + q0 + qr)) * Dd + lane * 2) = o;
    }
}

// ---------------- launch (single stream) ----------------
extern "C" void kernel_launch(void* const* d_in, const int* in_sizes, int n_in,
                              void* d_out, int out_size)
{
    const float*         q     = (const float*)d_in[0];
    const float*         k     = (const float*)d_in[1];
    const float*         v     = (const float*)d_in[2];
    const float*         scale = (const float*)d_in[3];
    const float*         prev  = (const float*)d_in[4];
    const float*         mask  = (const float*)d_in[5];
    const unsigned char* kpm   = (const unsigned char*)d_in[6];

    float* out    = (float*)d_out;
    float* attn   = out  + (size_t)BHn * Qlen * Dd;
    float* scores = attn + (size_t)BHn * QS;

    static int inited = 0;
    if (!inited) {
        cudaFuncSetAttribute(k1_scores, cudaFuncAttributeMaxDynamicSharedMemorySize, K1_SMEM);
        cudaFuncSetAttribute(k3_out,    cudaFuncAttributeMaxDynamicSharedMemorySize, K3_SMEM);
        inited = 1;
    }

    k0_q<<<4096, 256>>>(q);
    k0_k<<<dim3(Slen / 64, BHn), 256>>>(k);
    k0_v<<<dim3(Slen / 64, BHn), 256>>>(v);
    k1_scores<<<dim3(Slen / 128, Qlen / 64, BHn), 256, K1_SMEM>>>(prev, mask, kpm, scale, scores, attn);
    k3_out<<<dim3(Qlen / 128, BHn), 256, K3_SMEM>>>(scores, attn, out);
}

// round 15
// speedup vs baseline: 1.1025x; 1.1025x over previous
#include <cuda_runtime.h>
#include <cuda_bf16.h>
#include <stdint.h>

#define Qlen 2048
#define Slen 2048
#define Dd   64
#define BHn  32
#define NT   16
#define QS   (Qlen * Slen)
#define NROWS (BHn * Qlen)

// ---------------- device scratch (static, allowed) ----------------
__device__ __align__(16) __nv_bfloat16 g_qh[(size_t)BHn * Qlen * Dd];
__device__ __align__(16) __nv_bfloat16 g_ql[(size_t)BHn * Qlen * Dd];
__device__ __align__(16) __nv_bfloat16 g_kth[(size_t)BHn * Slen * Dd];  // k^T: [bh][s][d]
__device__ __align__(16) __nv_bfloat16 g_ktl[(size_t)BHn * Slen * Dd];
__device__ __align__(16) __nv_bfloat16 g_vth[(size_t)BHn * Dd * Slen];  // v^T: [bh][d][s]
__device__ __align__(16) __nv_bfloat16 g_vtl[(size_t)BHn * Dd * Slen];
__device__ float g_partial[(size_t)NROWS * NT];

// ---------------- warp MMA helpers (baseline PTX, sm_80+) ----------------
__device__ __forceinline__ uint32_t smem_u32(const void* p) {
    uint32_t a;
    asm("{ .reg .u64 t; cvta.to.shared.u64 t, %1; cvt.u32.u64 %0, t; }" : "=r"(a) : "l"(p));
    return a;
}
__device__ __forceinline__ void ldsm4(uint32_t (&r)[4], uint32_t addr) {
    asm volatile("ldmatrix.sync.aligned.m8n8.x4.shared.b16 {%0,%1,%2,%3}, [%4];"
        : "=r"(r[0]), "=r"(r[1]), "=r"(r[2]), "=r"(r[3]) : "r"(addr));
}
__device__ __forceinline__ void mma_bf16(float (&d)[4], const uint32_t (&a)[4],
                                         uint32_t b0, uint32_t b1) {
    asm volatile("mma.sync.aligned.m16n8k16.row.col.f32.bf16.bf16.f32 "
        "{%0,%1,%2,%3}, {%4,%5,%6,%7}, {%8,%9}, {%0,%1,%2,%3};"
        : "+f"(d[0]), "+f"(d[1]), "+f"(d[2]), "+f"(d[3])
        : "r"(a[0]), "r"(a[1]), "r"(a[2]), "r"(a[3]), "r"(b0), "r"(b1));
}
__device__ __forceinline__ void split4(float4 x, uint2& hi, uint2& lo) {
    __nv_bfloat16 h0 = __float2bfloat16_rn(x.x), h1 = __float2bfloat16_rn(x.y);
    __nv_bfloat16 h2 = __float2bfloat16_rn(x.z), h3 = __float2bfloat16_rn(x.w);
    float r0 = x.x - __bfloat162float(h0), r1 = x.y - __bfloat162float(h1);
    float r2 = x.z - __bfloat162float(h2), r3 = x.w - __bfloat162float(h3);
    __nv_bfloat162 a = {h0, h1}, b = {h2, h3};
    __nv_bfloat162 c = {__float2bfloat16_rn(r0), __float2bfloat16_rn(r1)};
    __nv_bfloat162 d = {__float2bfloat16_rn(r2), __float2bfloat16_rn(r3)};
    hi.x = *(uint32_t*)&a;  hi.y = *(uint32_t*)&b;
    lo.x = *(uint32_t*)&c;  lo.y = *(uint32_t*)&d;
}

#define SPB 144   // smem row stride in bytes for bf16 tiles (64 elems + 8 pad)
#define NINF __int_as_float(0xff800000)
#define NEG9 (-1.0e9f)

// ---------------- k0: conversions / transposes ----------------
__global__ __launch_bounds__(256) void k0_q(const float* __restrict__ Q) {
    int j = blockIdx.x * 256 + threadIdx.x;
    float4 x = ((const float4*)Q)[j];
    uint2 hi, lo; split4(x, hi, lo);
    ((uint2*)g_qh)[j] = hi;  ((uint2*)g_ql)[j] = lo;
}
__global__ __launch_bounds__(256) void k0_k(const float* __restrict__ K) {
    __shared__ float T[64][65];
    const int tid = threadIdx.x, bh = blockIdx.y, s0 = blockIdx.x * 64;
    const int r = tid >> 4, c4 = tid & 15;
    #pragma unroll
    for (int i = 0; i < 4; ++i) {
        int d = r + i * 16;
        float4 x = *(const float4*)(K + ((size_t)(bh * Dd + d)) * Slen + s0 + c4 * 4);
        T[d][c4 * 4] = x.x; T[d][c4 * 4 + 1] = x.y; T[d][c4 * 4 + 2] = x.z; T[d][c4 * 4 + 3] = x.w;
    }
    __syncthreads();
    #pragma unroll
    for (int i = 0; i < 4; ++i) {
        int s = r + i * 16;
        float4 x = make_float4(T[c4 * 4][s], T[c4 * 4 + 1][s], T[c4 * 4 + 2][s], T[c4 * 4 + 3][s]);
        uint2 hi, lo; split4(x, hi, lo);
        size_t off = ((size_t)(bh * Slen + s0 + s)) * Dd + c4 * 4;
        ((uint2*)g_kth)[off >> 2] = hi;  ((uint2*)g_ktl)[off >> 2] = lo;
    }
}
__global__ __launch_bounds__(256) void k0_v(const float* __restrict__ V) {
    __shared__ float T[64][65];
    const int tid = threadIdx.x, bh = blockIdx.y, s0 = blockIdx.x * 64;
    const int r = tid >> 4, c4 = tid & 15;
    #pragma unroll
    for (int i = 0; i < 4; ++i) {
        int s = r + i * 16;
        float4 x = *(const float4*)(V + ((size_t)(bh * Slen + s0 + s)) * Dd + c4 * 4);
        T[s][c4 * 4] = x.x; T[s][c4 * 4 + 1] = x.y; T[s][c4 * 4 + 2] = x.z; T[s][c4 * 4 + 3] = x.w;
    }
    __syncthreads();
    #pragma unroll
    for (int i = 0; i < 4; ++i) {
        int d = r + i * 16;
        float4 x = make_float4(T[c4 * 4][d], T[c4 * 4 + 1][d], T[c4 * 4 + 2][d], T[c4 * 4 + 3][d]);
        uint2 hi, lo; split4(x, hi, lo);
        size_t off = ((size_t)(bh * Dd + d)) * Slen + s0 + c4 * 4;
        ((uint2*)g_vth)[off >> 2] = hi;  ((uint2*)g_vtl)[off >> 2] = lo;
    }
}

// ---------------- k1: 64x128 tile, causal-aware, 3 CTAs/SM ------------------
// Fill tiles also zero the attn output. q processed in DESCENDING order so the
// all-compute high-q rows start first (shorter tail).
// smem bytes: Qh@0 (64x144=9216), Ql@9216, Kh@18432 (128x144=18432), Kl@36864.
// Dst (float, 64 x 132 = 33792 B) aliased at 0 after MMA. Total 55296.
#define K1_SMEM 55296
__global__ __launch_bounds__(256, 3) void k1_scores(
    const float* __restrict__ Pp, const float* __restrict__ Mp,
    const unsigned char* __restrict__ KPM, const float* __restrict__ Sc,
    float* __restrict__ OutS, float* __restrict__ OutA)
{
    extern __shared__ char smem[];
    const uint32_t sb = smem_u32(smem);
    float* Dst = (float*)smem;
    const int tid = threadIdx.x, wid = tid >> 5, lane = tid & 31;
    const int bh = blockIdx.z, q0 = (31 - (int)blockIdx.y) * 64, s0 = blockIdx.x * 128, b = bh >> 4;

    // ---- fully-masked tile (s > q everywhere): scores = -1e9, attn = 0 ----
    if (s0 >= q0 + 64) {
        const float4 neg = make_float4(NEG9, NEG9, NEG9, NEG9);
        const float4 zer = make_float4(0.f, 0.f, 0.f, 0.f);
        const size_t base = (size_t)bh * QS + (size_t)q0 * Slen + s0;
        #pragma unroll
        for (int i = 0; i < 8; ++i) {
            int j = tid + i * 256;               // 2048 float4 = 64 rows x 32
            int row = j >> 5, c = j & 31;
            size_t off = base + (size_t)row * Slen + c * 4;
            __stcs((float4*)(OutS + off), neg);
            __stcs((float4*)(OutA + off), zer);
        }
        if (tid < 64)
            g_partial[((size_t)(bh * Qlen + q0 + tid)) * NT + blockIdx.x] = 0.f;
        return;
    }
    const bool needMask = (s0 + 127 > q0);       // any masked element in tile?
    const float scale = *Sc;

    // stage operands: Q 64 rows, K 128 rows (each 128B/row at stride 144B)
    {
        const uint4* qh = (const uint4*)(g_qh + ((size_t)(bh * Qlen + q0)) * Dd);
        const uint4* ql = (const uint4*)(g_ql + ((size_t)(bh * Qlen + q0)) * Dd);
        #pragma unroll
        for (int i = 0; i < 2; ++i) {
            int j = tid + i * 256;
            int r = j >> 3, c = j & 7;
            uint32_t so = r * SPB + c * 16;
            *(uint4*)(smem + so)        = qh[j];
            *(uint4*)(smem + 9216 + so) = ql[j];
        }
        const uint4* kh = (const uint4*)(g_kth + ((size_t)(bh * Slen + s0)) * Dd);
        const uint4* kl = (const uint4*)(g_ktl + ((size_t)(bh * Slen + s0)) * Dd);
        #pragma unroll
        for (int i = 0; i < 4; ++i) {
            int j = tid + i * 256;
            int r = j >> 3, c = j & 7;
            uint32_t so = r * SPB + c * 16;
            *(uint4*)(smem + 18432 + so) = kh[j];
            *(uint4*)(smem + 36864 + so) = kl[j];
        }
    }
    __syncthreads();

    const int warp_m0 = (wid & 3) * 16;
    const int warp_n0 = (wid >> 2) * 64;
    const int quad = lane >> 3, rq = lane & 7;
    const int a_row = ((quad & 1) << 3) + rq;
    const int a_colb = ((quad >> 1) << 4);
    const int b_nfl = quad >> 1;
    const int b_kofb = ((quad & 1) << 4);

    float acc[8][4] = {};
    #pragma unroll
    for (int ks = 0; ks < 4; ++ks) {
        uint32_t ah[4], al[4];
        {
            uint32_t off = (uint32_t)(warp_m0 + a_row) * SPB + ks * 32 + a_colb;
            ldsm4(ah, sb + off);
            ldsm4(al, sb + 9216 + off);
        }
        #pragma unroll
        for (int p = 0; p < 4; ++p) {
            uint32_t off = (uint32_t)(warp_n0 + (p * 2 + b_nfl) * 8 + rq) * SPB + ks * 32 + b_kofb;
            uint32_t th[4], tl[4];
            ldsm4(th, sb + 18432 + off);
            ldsm4(tl, sb + 36864 + off);
            mma_bf16(acc[p * 2],     ah, th[0], th[1]);
            mma_bf16(acc[p * 2],     al, th[0], th[1]);
            mma_bf16(acc[p * 2],     ah, tl[0], tl[1]);
            mma_bf16(acc[p * 2 + 1], ah, th[2], th[3]);
            mma_bf16(acc[p * 2 + 1], al, th[2], th[3]);
            mma_bf16(acc[p * 2 + 1], ah, tl[2], tl[3]);
        }
    }
    __syncthreads();   // operands dead; alias Dst over them

    // acc -> smem stage (stride 132 floats => float4-aligned reads)
    {
        const int g = lane >> 2, t2 = (lane & 3) * 2;
        #pragma unroll
        for (int nf = 0; nf < 8; ++nf) {
            int row = warp_m0 + g;
            int col = warp_n0 + nf * 8 + t2;
            *(float2*)&Dst[row * 132 + col]       = make_float2(acc[nf][0], acc[nf][1]);
            *(float2*)&Dst[(row + 8) * 132 + col] = make_float2(acc[nf][2], acc[nf][3]);
        }
    }
    __syncthreads();

    // epilogue: 8 rows per warp in 2 batches of 4; batched loads for MLP
    {
        const uchar4 kp = *(const uchar4*)(KPM + b * Slen + s0 + lane * 4);
        #pragma unroll
        for (int half = 0; half < 2; ++half) {
            float4 pv[4], mv[4];
            #pragma unroll
            for (int it = 0; it < 4; ++it) {
                int qg = q0 + wid * 8 + half * 4 + it;
                pv[it] = __ldcs((const float4*)(Pp + (size_t)bh * QS + (size_t)qg * Slen + s0 + lane * 4));
                if (needMask)
                    mv[it] = *(const float4*)(Mp + (size_t)qg * Slen + s0 + lane * 4);
                else
                    mv[it] = make_float4(0.f, 0.f, 0.f, 0.f);
            }
            #pragma unroll
            for (int it = 0; it < 4; ++it) {
                int qr = wid * 8 + half * 4 + it, qg = q0 + qr;
                float4 dv = *(const float4*)(Dst + qr * 132 + lane * 4);
                float4 r;
                r.x = fmaf(dv.x, scale, pv[it].x) + mv[it].x;
                r.y = fmaf(dv.y, scale, pv[it].y) + mv[it].y;
                r.z = fmaf(dv.z, scale, pv[it].z) + mv[it].z;
                r.w = fmaf(dv.w, scale, pv[it].w) + mv[it].w;
                if (kp.x) r.x = NINF;
                if (kp.y) r.y = NINF;
                if (kp.z) r.z = NINF;
                if (kp.w) r.w = NINF;
                __stcs((float4*)(OutS + (size_t)bh * QS + (size_t)qg * Slen + s0 + lane * 4), r);
                float e = __expf(r.x) + __expf(r.y) + __expf(r.z) + __expf(r.w);
                #pragma unroll
                for (int o = 16; o; o >>= 1) e += __shfl_xor_sync(0xffffffffu, e, o);
                if (lane == 0) g_partial[((size_t)(bh * Qlen + qg)) * NT + blockIdx.x] = e;
            }
        }
    }
}

// ---------------- k3: causal-aware attn write + out = attn @ v --------------
// R13 inner loop (single buffer, register prefetch). Rowsum reduce inlined
// (k2 eliminated). q processed in DESCENDING order (longest CTAs first).
// smem bytes: Ah@0 (128x144), Al@18432, Bh@36864 (64x144), Bl@46080, inv@55296.
// Dst (float, 128 x 66) aliased at 0 for the final epilogue. Total 55808.
#define K3_SMEM 55808
__global__ __launch_bounds__(256, 2) void k3_out(
    const float* __restrict__ S, float* __restrict__ A, float* __restrict__ O)
{
    extern __shared__ char smem[];
    const uint32_t sb = smem_u32(smem);
    float* smInv = (float*)(smem + 55296);
    float* Dst = (float*)smem;
    const int tid = threadIdx.x, wid = tid >> 5, lane = tid & 31;
    const int qb = 15 - (int)blockIdx.x;                 // descending q order
    const int bh = blockIdx.y, q0 = qb * 128;
    const int cmax = min(32, 2 * qb + 2);                // chunks with any s <= q

    // inline rowsum reduce (replaces k2)
    if (tid < 128) {
        const float4* p = (const float4*)(g_partial + (size_t)(bh * Qlen + q0 + tid) * NT);
        float4 a = p[0], b = p[1], c = p[2], d = p[3];
        float s = a.x + a.y + a.z + a.w + b.x + b.y + b.z + b.w
                + c.x + c.y + c.z + c.w + d.x + d.y + d.z + d.w;
        smInv[tid] = 1.0f / s;
    }
    __syncthreads();

    const size_t sbase = (size_t)bh * QS + (size_t)q0 * Slen;
    const uint4* vh = (const uint4*)(g_vth + (size_t)bh * Dd * Slen);
    const uint4* vl = (const uint4*)(g_vtl + (size_t)bh * Dd * Slen);

    const int warp_m0 = (wid & 1) * 64;
    const int warp_n0 = (wid >> 1) * 16;
    const int quad = lane >> 3, rq = lane & 7;
    const int a_row = ((quad & 1) << 3) + rq;
    const int a_colb = ((quad >> 1) << 4);
    const int b_nfl = quad >> 1;
    const int b_kofb = ((quad & 1) << 4);

    const int sqr = tid >> 4, sf4 = tid & 15;
    const int vd  = tid >> 3, vc8 = tid & 7;

    float acc[4][2][4] = {};
    float4 xr[8];
    uint4  vb[2][2];

    #pragma unroll
    for (int i = 0; i < 8; ++i)
        xr[i] = __ldcs((const float4*)(S + sbase + (size_t)(sqr + i * 16) * Slen + sf4 * 4));
    #pragma unroll
    for (int i = 0; i < 2; ++i) {
        size_t eidx = (((size_t)(vd + i * 32) * Slen) >> 3) + vc8;
        vb[i][0] = vh[eidx];  vb[i][1] = vl[eidx];
    }

    for (int c = 0; c < cmax; ++c) {
        #pragma unroll
        for (int i = 0; i < 8; ++i) {
            int qr = sqr + i * 16;
            float iv = smInv[qr];
            float4 p;
            p.x = __expf(xr[i].x) * iv;  p.y = __expf(xr[i].y) * iv;
            p.z = __expf(xr[i].z) * iv;  p.w = __expf(xr[i].w) * iv;
            __stcs((float4*)(A + sbase + (size_t)qr * Slen + c * 64 + sf4 * 4), p);
            uint2 hi, lo; split4(p, hi, lo);
            uint32_t so = (uint32_t)qr * SPB + sf4 * 8;
            *(uint2*)(smem + so)         = hi;
            *(uint2*)(smem + 18432 + so) = lo;
        }
        #pragma unroll
        for (int i = 0; i < 2; ++i) {
            uint32_t so = (uint32_t)(vd + i * 32) * SPB + vc8 * 16;
            *(uint4*)(smem + 36864 + so) = vb[i][0];
            *(uint4*)(smem + 46080 + so) = vb[i][1];
        }
        __syncthreads();

        if (c + 1 < cmax) {
            #pragma unroll
            for (int i = 0; i < 8; ++i)
                xr[i] = __ldcs((const float4*)(S + sbase + (size_t)(sqr + i * 16) * Slen + (c + 1) * 64 + sf4 * 4));
            #pragma unroll
            for (int i = 0; i < 2; ++i) {
                size_t eidx = (((size_t)(vd + i * 32) * Slen + (c + 1) * 64) >> 3) + vc8;
                vb[i][0] = vh[eidx];  vb[i][1] = vl[eidx];
            }
        }

        #pragma unroll
        for (int ks = 0; ks < 4; ++ks) {
            uint32_t bhf[4], blf[4];
            {
                uint32_t off = (uint32_t)(warp_n0 + b_nfl * 8 + rq) * SPB + ks * 32 + b_kofb;
                ldsm4(bhf, sb + 36864 + off);
                ldsm4(blf, sb + 46080 + off);
            }
            #pragma unroll
            for (int mf = 0; mf < 4; ++mf) {
                uint32_t ah[4], al[4];
                uint32_t off = (uint32_t)(warp_m0 + mf * 16 + a_row) * SPB + ks * 32 + a_colb;
                ldsm4(ah, sb + off);
                ldsm4(al, sb + 18432 + off);
                mma_bf16(acc[mf][0], ah, bhf[0], bhf[1]);
                mma_bf16(acc[mf][0], al, bhf[0], bhf[1]);
                mma_bf16(acc[mf][0], ah, blf[0], blf[1]);
                mma_bf16(acc[mf][1], ah, bhf[2], bhf[3]);
                mma_bf16(acc[mf][1], al, bhf[2], bhf[3]);
                mma_bf16(acc[mf][1], ah, blf[2], blf[3]);
            }
        }
        __syncthreads();
    }

    {
        const int g = lane >> 2, t2 = (lane & 3) * 2;
        #pragma unroll
        for (int mf = 0; mf < 4; ++mf)
            #pragma unroll
            for (int nf = 0; nf < 2; ++nf) {
                int row = warp_m0 + mf * 16 + g;
                int col = warp_n0 + nf * 8 + t2;
                *(float2*)&Dst[row * 66 + col]       = make_float2(acc[mf][nf][0], acc[mf][nf][1]);
                *(float2*)&Dst[(row + 8) * 66 + col] = make_float2(acc[mf][nf][2], acc[mf][nf][3]);
            }
    }
    __syncthreads();
    #pragma unroll
    for (int it = 0; it < 16; ++it) {
        int qr = wid * 16 + it;
        float2 o = *(const float2*)(Dst + qr * 66 + lane * 2);
        *(float2*)(O + ((size_t)(bh * Qlen + q0 + qr)) * Dd + lane * 2) = o;
    }
}

// ---------------- launch (single stream) ----------------
extern "C" void kernel_launch(void* const* d_in, const int* in_sizes, int n_in,
                              void* d_out, int out_size)
{
    const float*         q     = (const float*)d_in[0];
    const float*         k     = (const float*)d_in[1];
    const float*         v     = (const float*)d_in[2];
    const float*         scale = (const float*)d_in[3];
    const float*         prev  = (const float*)d_in[4];
    const float*         mask  = (const float*)d_in[5];
    const unsigned char* kpm   = (const unsigned char*)d_in[6];

    float* out    = (float*)d_out;
    float* attn   = out  + (size_t)BHn * Qlen * Dd;
    float* scores = attn + (size_t)BHn * QS;

    static int inited = 0;
    if (!inited) {
        cudaFuncSetAttribute(k1_scores, cudaFuncAttributeMaxDynamicSharedMemorySize, K1_SMEM);
        cudaFuncSetAttribute(k3_out,    cudaFuncAttributeMaxDynamicSharedMemorySize, K3_SMEM);
        inited = 1;
    }

    k0_q<<<4096, 256>>>(q);
    k0_k<<<dim3(Slen / 64, BHn), 256>>>(k);
    k0_v<<<dim3(Slen / 64, BHn), 256>>>(v);
    k1_scores<<<dim3(Slen / 128, Qlen / 64, BHn), 256, K1_SMEM>>>(prev, mask, kpm, scale, scores, attn);
    k3_out<<<dim3(Qlen / 128, BHn), 256, K3_SMEM>>>(scores, attn, out);
}

// round 16
// speedup vs baseline: 1.1174x; 1.0136x over previous
#include <cuda_runtime.h>
#include <cuda_bf16.h>
#include <stdint.h>

#define Qlen 2048
#define Slen 2048
#define Dd   64
#define BHn  32
#define NT   16
#define QS   (Qlen * Slen)
#define NROWS (BHn * Qlen)

// ---------------- device scratch (static, allowed) ----------------
__device__ __align__(16) __nv_bfloat16 g_qh[(size_t)BHn * Qlen * Dd];
__device__ __align__(16) __nv_bfloat16 g_ql[(size_t)BHn * Qlen * Dd];
__device__ __align__(16) __nv_bfloat16 g_kth[(size_t)BHn * Slen * Dd];  // k^T: [bh][s][d]
__device__ __align__(16) __nv_bfloat16 g_ktl[(size_t)BHn * Slen * Dd];
__device__ __align__(16) __nv_bfloat16 g_vth[(size_t)BHn * Dd * Slen];  // v^T: [bh][d][s]
__device__ __align__(16) __nv_bfloat16 g_vtl[(size_t)BHn * Dd * Slen];
__device__ float g_partial[(size_t)NROWS * NT];

// ---------------- warp MMA helpers (baseline PTX, sm_80+) ----------------
__device__ __forceinline__ uint32_t smem_u32(const void* p) {
    uint32_t a;
    asm("{ .reg .u64 t; cvta.to.shared.u64 t, %1; cvt.u32.u64 %0, t; }" : "=r"(a) : "l"(p));
    return a;
}
__device__ __forceinline__ void ldsm4(uint32_t (&r)[4], uint32_t addr) {
    asm volatile("ldmatrix.sync.aligned.m8n8.x4.shared.b16 {%0,%1,%2,%3}, [%4];"
        : "=r"(r[0]), "=r"(r[1]), "=r"(r[2]), "=r"(r[3]) : "r"(addr));
}
__device__ __forceinline__ void mma_bf16(float (&d)[4], const uint32_t (&a)[4],
                                         uint32_t b0, uint32_t b1) {
    asm volatile("mma.sync.aligned.m16n8k16.row.col.f32.bf16.bf16.f32 "
        "{%0,%1,%2,%3}, {%4,%5,%6,%7}, {%8,%9}, {%0,%1,%2,%3};"
        : "+f"(d[0]), "+f"(d[1]), "+f"(d[2]), "+f"(d[3])
        : "r"(a[0]), "r"(a[1]), "r"(a[2]), "r"(a[3]), "r"(b0), "r"(b1));
}
__device__ __forceinline__ void split4(float4 x, uint2& hi, uint2& lo) {
    __nv_bfloat16 h0 = __float2bfloat16_rn(x.x), h1 = __float2bfloat16_rn(x.y);
    __nv_bfloat16 h2 = __float2bfloat16_rn(x.z), h3 = __float2bfloat16_rn(x.w);
    float r0 = x.x - __bfloat162float(h0), r1 = x.y - __bfloat162float(h1);
    float r2 = x.z - __bfloat162float(h2), r3 = x.w - __bfloat162float(h3);
    __nv_bfloat162 a = {h0, h1}, b = {h2, h3};
    __nv_bfloat162 c = {__float2bfloat16_rn(r0), __float2bfloat16_rn(r1)};
    __nv_bfloat162 d = {__float2bfloat16_rn(r2), __float2bfloat16_rn(r3)};
    hi.x = *(uint32_t*)&a;  hi.y = *(uint32_t*)&b;
    lo.x = *(uint32_t*)&c;  lo.y = *(uint32_t*)&d;
}

#define SPB 144   // smem row stride in bytes for bf16 tiles (64 elems + 8 pad)
#define NINF __int_as_float(0xff800000)
#define NEG9 (-1.0e9f)

// ---------------- k0: all conversions / transposes in ONE launch ------------
// grid: [0,4096)   -> q split (streaming)
//       [4096,5120)-> k transpose: idx = x-4096, sc = idx & 31, bh = idx >> 5
//       [5120,6144)-> v transpose: idx = x-5120, sc = idx & 31, bh = idx >> 5
__global__ __launch_bounds__(256) void k0_all(
    const float* __restrict__ Q, const float* __restrict__ K,
    const float* __restrict__ V)
{
    __shared__ float T[64][65];
    const int tid = threadIdx.x;
    const int bx = blockIdx.x;

    if (bx < 4096) {                               // ---- q conversion ----
        int j = bx * 256 + tid;
        float4 x = ((const float4*)Q)[j];
        uint2 hi, lo; split4(x, hi, lo);
        ((uint2*)g_qh)[j] = hi;  ((uint2*)g_ql)[j] = lo;
        return;
    }

    const int r = tid >> 4, c4 = tid & 15;
    if (bx < 5120) {                               // ---- k transpose ----
        const int idx = bx - 4096, sc = idx & 31, bh = idx >> 5;
        const int s0 = sc * 64;
        #pragma unroll
        for (int i = 0; i < 4; ++i) {
            int d = r + i * 16;
            float4 x = *(const float4*)(K + ((size_t)(bh * Dd + d)) * Slen + s0 + c4 * 4);
            T[d][c4 * 4] = x.x; T[d][c4 * 4 + 1] = x.y; T[d][c4 * 4 + 2] = x.z; T[d][c4 * 4 + 3] = x.w;
        }
        __syncthreads();
        #pragma unroll
        for (int i = 0; i < 4; ++i) {
            int s = r + i * 16;
            float4 x = make_float4(T[c4 * 4][s], T[c4 * 4 + 1][s], T[c4 * 4 + 2][s], T[c4 * 4 + 3][s]);
            uint2 hi, lo; split4(x, hi, lo);
            size_t off = ((size_t)(bh * Slen + s0 + s)) * Dd + c4 * 4;
            ((uint2*)g_kth)[off >> 2] = hi;  ((uint2*)g_ktl)[off >> 2] = lo;
        }
    } else {                                       // ---- v transpose ----
        const int idx = bx - 5120, sc = idx & 31, bh = idx >> 5;
        const int s0 = sc * 64;
        #pragma unroll
        for (int i = 0; i < 4; ++i) {
            int s = r + i * 16;
            float4 x = *(const float4*)(V + ((size_t)(bh * Slen + s0 + s)) * Dd + c4 * 4);
            T[s][c4 * 4] = x.x; T[s][c4 * 4 + 1] = x.y; T[s][c4 * 4 + 2] = x.z; T[s][c4 * 4 + 3] = x.w;
        }
        __syncthreads();
        #pragma unroll
        for (int i = 0; i < 4; ++i) {
            int d = r + i * 16;
            float4 x = make_float4(T[c4 * 4][d], T[c4 * 4 + 1][d], T[c4 * 4 + 2][d], T[c4 * 4 + 3][d]);
            uint2 hi, lo; split4(x, hi, lo);
            size_t off = ((size_t)(bh * Dd + d)) * Slen + s0 + c4 * 4;
            ((uint2*)g_vth)[off >> 2] = hi;  ((uint2*)g_vtl)[off >> 2] = lo;
        }
    }
}

// ---------------- k1: 64x128 tile, causal-aware, 3 CTAs/SM ------------------
// Fill tiles also zero the attn output. q processed in DESCENDING order.
// smem bytes: Qh@0 (64x144=9216), Ql@9216, Kh@18432 (128x144=18432), Kl@36864.
// Dst (float, 64 x 132 = 33792 B) aliased at 0 after MMA. Total 55296.
#define K1_SMEM 55296
__global__ __launch_bounds__(256, 3) void k1_scores(
    const float* __restrict__ Pp, const float* __restrict__ Mp,
    const unsigned char* __restrict__ KPM, const float* __restrict__ Sc,
    float* __restrict__ OutS, float* __restrict__ OutA)
{
    extern __shared__ char smem[];
    const uint32_t sb = smem_u32(smem);
    float* Dst = (float*)smem;
    const int tid = threadIdx.x, wid = tid >> 5, lane = tid & 31;
    const int bh = blockIdx.z, q0 = (31 - (int)blockIdx.y) * 64, s0 = blockIdx.x * 128, b = bh >> 4;

    // ---- fully-masked tile (s > q everywhere): scores = -1e9, attn = 0 ----
    if (s0 >= q0 + 64) {
        const float4 neg = make_float4(NEG9, NEG9, NEG9, NEG9);
        const float4 zer = make_float4(0.f, 0.f, 0.f, 0.f);
        const size_t base = (size_t)bh * QS + (size_t)q0 * Slen + s0;
        #pragma unroll
        for (int i = 0; i < 8; ++i) {
            int j = tid + i * 256;               // 2048 float4 = 64 rows x 32
            int row = j >> 5, c = j & 31;
            size_t off = base + (size_t)row * Slen + c * 4;
            __stcs((float4*)(OutS + off), neg);
            __stcs((float4*)(OutA + off), zer);
        }
        if (tid < 64)
            g_partial[((size_t)(bh * Qlen + q0 + tid)) * NT + blockIdx.x] = 0.f;
        return;
    }
    const bool needMask = (s0 + 127 > q0);       // any masked element in tile?
    const float scale = *Sc;

    // stage operands: Q 64 rows, K 128 rows (each 128B/row at stride 144B)
    {
        const uint4* qh = (const uint4*)(g_qh + ((size_t)(bh * Qlen + q0)) * Dd);
        const uint4* ql = (const uint4*)(g_ql + ((size_t)(bh * Qlen + q0)) * Dd);
        #pragma unroll
        for (int i = 0; i < 2; ++i) {
            int j = tid + i * 256;
            int r = j >> 3, c = j & 7;
            uint32_t so = r * SPB + c * 16;
            *(uint4*)(smem + so)        = qh[j];
            *(uint4*)(smem + 9216 + so) = ql[j];
        }
        const uint4* kh = (const uint4*)(g_kth + ((size_t)(bh * Slen + s0)) * Dd);
        const uint4* kl = (const uint4*)(g_ktl + ((size_t)(bh * Slen + s0)) * Dd);
        #pragma unroll
        for (int i = 0; i < 4; ++i) {
            int j = tid + i * 256;
            int r = j >> 3, c = j & 7;
            uint32_t so = r * SPB + c * 16;
            *(uint4*)(smem + 18432 + so) = kh[j];
            *(uint4*)(smem + 36864 + so) = kl[j];
        }
    }
    __syncthreads();

    const int warp_m0 = (wid & 3) * 16;
    const int warp_n0 = (wid >> 2) * 64;
    const int quad = lane >> 3, rq = lane & 7;
    const int a_row = ((quad & 1) << 3) + rq;
    const int a_colb = ((quad >> 1) << 4);
    const int b_nfl = quad >> 1;
    const int b_kofb = ((quad & 1) << 4);

    float acc[8][4] = {};
    #pragma unroll
    for (int ks = 0; ks < 4; ++ks) {
        uint32_t ah[4], al[4];
        {
            uint32_t off = (uint32_t)(warp_m0 + a_row) * SPB + ks * 32 + a_colb;
            ldsm4(ah, sb + off);
            ldsm4(al, sb + 9216 + off);
        }
        #pragma unroll
        for (int p = 0; p < 4; ++p) {
            uint32_t off = (uint32_t)(warp_n0 + (p * 2 + b_nfl) * 8 + rq) * SPB + ks * 32 + b_kofb;
            uint32_t th[4], tl[4];
            ldsm4(th, sb + 18432 + off);
            ldsm4(tl, sb + 36864 + off);
            mma_bf16(acc[p * 2],     ah, th[0], th[1]);
            mma_bf16(acc[p * 2],     al, th[0], th[1]);
            mma_bf16(acc[p * 2],     ah, tl[0], tl[1]);
            mma_bf16(acc[p * 2 + 1], ah, th[2], th[3]);
            mma_bf16(acc[p * 2 + 1], al, th[2], th[3]);
            mma_bf16(acc[p * 2 + 1], ah, tl[2], tl[3]);
        }
    }
    __syncthreads();   // operands dead; alias Dst over them

    // acc -> smem stage (stride 132 floats => float4-aligned reads)
    {
        const int g = lane >> 2, t2 = (lane & 3) * 2;
        #pragma unroll
        for (int nf = 0; nf < 8; ++nf) {
            int row = warp_m0 + g;
            int col = warp_n0 + nf * 8 + t2;
            *(float2*)&Dst[row * 132 + col]       = make_float2(acc[nf][0], acc[nf][1]);
            *(float2*)&Dst[(row + 8) * 132 + col] = make_float2(acc[nf][2], acc[nf][3]);
        }
    }
    __syncthreads();

    // epilogue: 8 rows per warp in 2 batches of 4; batched loads for MLP
    {
        const uchar4 kp = *(const uchar4*)(KPM + b * Slen + s0 + lane * 4);
        #pragma unroll
        for (int half = 0; half < 2; ++half) {
            float4 pv[4], mv[4];
            #pragma unroll
            for (int it = 0; it < 4; ++it) {
                int qg = q0 + wid * 8 + half * 4 + it;
                pv[it] = __ldcs((const float4*)(Pp + (size_t)bh * QS + (size_t)qg * Slen + s0 + lane * 4));
                if (needMask)
                    mv[it] = *(const float4*)(Mp + (size_t)qg * Slen + s0 + lane * 4);
                else
                    mv[it] = make_float4(0.f, 0.f, 0.f, 0.f);
            }
            #pragma unroll
            for (int it = 0; it < 4; ++it) {
                int qr = wid * 8 + half * 4 + it, qg = q0 + qr;
                float4 dv = *(const float4*)(Dst + qr * 132 + lane * 4);
                float4 r;
                r.x = fmaf(dv.x, scale, pv[it].x) + mv[it].x;
                r.y = fmaf(dv.y, scale, pv[it].y) + mv[it].y;
                r.z = fmaf(dv.z, scale, pv[it].z) + mv[it].z;
                r.w = fmaf(dv.w, scale, pv[it].w) + mv[it].w;
                if (kp.x) r.x = NINF;
                if (kp.y) r.y = NINF;
                if (kp.z) r.z = NINF;
                if (kp.w) r.w = NINF;
                __stcs((float4*)(OutS + (size_t)bh * QS + (size_t)qg * Slen + s0 + lane * 4), r);
                float e = __expf(r.x) + __expf(r.y) + __expf(r.z) + __expf(r.w);
                #pragma unroll
                for (int o = 16; o; o >>= 1) e += __shfl_xor_sync(0xffffffffu, e, o);
                if (lane == 0) g_partial[((size_t)(bh * Qlen + qg)) * NT + blockIdx.x] = e;
            }
        }
    }
}

// ---------------- k3: causal-aware attn write + out = attn @ v --------------
// Single-buffer inner loop with register prefetch; rowsum reduce inlined.
// smem bytes: Ah@0 (128x144), Al@18432, Bh@36864 (64x144), Bl@46080, inv@55296.
// Dst (float, 128 x 66) aliased at 0 for the final epilogue. Total 55808.
#define K3_SMEM 55808
__global__ __launch_bounds__(256, 2) void k3_out(
    const float* __restrict__ S, float* __restrict__ A, float* __restrict__ O)
{
    extern __shared__ char smem[];
    const uint32_t sb = smem_u32(smem);
    float* smInv = (float*)(smem + 55296);
    float* Dst = (float*)smem;
    const int tid = threadIdx.x, wid = tid >> 5, lane = tid & 31;
    const int qb = 15 - (int)blockIdx.x;                 // descending q order
    const int bh = blockIdx.y, q0 = qb * 128;
    const int cmax = min(32, 2 * qb + 2);                // chunks with any s <= q

    // inline rowsum reduce (k2 eliminated)
    if (tid < 128) {
        const float4* p = (const float4*)(g_partial + (size_t)(bh * Qlen + q0 + tid) * NT);
        float4 a = p[0], b = p[1], c = p[2], d = p[3];
        float s = a.x + a.y + a.z + a.w + b.x + b.y + b.z + b.w
                + c.x + c.y + c.z + c.w + d.x + d.y + d.z + d.w;
        smInv[tid] = 1.0f / s;
    }
    __syncthreads();

    const size_t sbase = (size_t)bh * QS + (size_t)q0 * Slen;
    const uint4* vh = (const uint4*)(g_vth + (size_t)bh * Dd * Slen);
    const uint4* vl = (const uint4*)(g_vtl + (size_t)bh * Dd * Slen);

    const int warp_m0 = (wid & 1) * 64;
    const int warp_n0 = (wid >> 1) * 16;
    const int quad = lane >> 3, rq = lane & 7;
    const int a_row = ((quad & 1) << 3) + rq;
    const int a_colb = ((quad >> 1) << 4);
    const int b_nfl = quad >> 1;
    const int b_kofb = ((quad & 1) << 4);

    const int sqr = tid >> 4, sf4 = tid & 15;
    const int vd  = tid >> 3, vc8 = tid & 7;

    float acc[4][2][4] = {};
    float4 xr[8];
    uint4  vb[2][2];

    #pragma unroll
    for (int i = 0; i < 8; ++i)
        xr[i] = __ldcs((const float4*)(S + sbase + (size_t)(sqr + i * 16) * Slen + sf4 * 4));
    #pragma unroll
    for (int i = 0; i < 2; ++i) {
        size_t eidx = (((size_t)(vd + i * 32) * Slen) >> 3) + vc8;
        vb[i][0] = vh[eidx];  vb[i][1] = vl[eidx];
    }

    for (int c = 0; c < cmax; ++c) {
        #pragma unroll
        for (int i = 0; i < 8; ++i) {
            int qr = sqr + i * 16;
            float iv = smInv[qr];
            float4 p;
            p.x = __expf(xr[i].x) * iv;  p.y = __expf(xr[i].y) * iv;
            p.z = __expf(xr[i].z) * iv;  p.w = __expf(xr[i].w) * iv;
            __stcs((float4*)(A + sbase + (size_t)qr * Slen + c * 64 + sf4 * 4), p);
            uint2 hi, lo; split4(p, hi, lo);
            uint32_t so = (uint32_t)qr * SPB + sf4 * 8;
            *(uint2*)(smem + so)         = hi;
            *(uint2*)(smem + 18432 + so) = lo;
        }
        #pragma unroll
        for (int i = 0; i < 2; ++i) {
            uint32_t so = (uint32_t)(vd + i * 32) * SPB + vc8 * 16;
            *(uint4*)(smem + 36864 + so) = vb[i][0];
            *(uint4*)(smem + 46080 + so) = vb[i][1];
        }
        __syncthreads();

        if (c + 1 < cmax) {
            #pragma unroll
            for (int i = 0; i < 8; ++i)
                xr[i] = __ldcs((const float4*)(S + sbase + (size_t)(sqr + i * 16) * Slen + (c + 1) * 64 + sf4 * 4));
            #pragma unroll
            for (int i = 0; i < 2; ++i) {
                size_t eidx = (((size_t)(vd + i * 32) * Slen + (c + 1) * 64) >> 3) + vc8;
                vb[i][0] = vh[eidx];  vb[i][1] = vl[eidx];
            }
        }

        #pragma unroll
        for (int ks = 0; ks < 4; ++ks) {
            uint32_t bhf[4], blf[4];
            {
                uint32_t off = (uint32_t)(warp_n0 + b_nfl * 8 + rq) * SPB + ks * 32 + b_kofb;
                ldsm4(bhf, sb + 36864 + off);
                ldsm4(blf, sb + 46080 + off);
            }
            #pragma unroll
            for (int mf = 0; mf < 4; ++mf) {
                uint32_t ah[4], al[4];
                uint32_t off = (uint32_t)(warp_m0 + mf * 16 + a_row) * SPB + ks * 32 + a_colb;
                ldsm4(ah, sb + off);
                ldsm4(al, sb + 18432 + off);
                mma_bf16(acc[mf][0], ah, bhf[0], bhf[1]);
                mma_bf16(acc[mf][0], al, bhf[0], bhf[1]);
                mma_bf16(acc[mf][0], ah, blf[0], blf[1]);
                mma_bf16(acc[mf][1], ah, bhf[2], bhf[3]);
                mma_bf16(acc[mf][1], al, bhf[2], bhf[3]);
                mma_bf16(acc[mf][1], ah, blf[2], blf[3]);
            }
        }
        __syncthreads();
    }

    {
        const int g = lane >> 2, t2 = (lane & 3) * 2;
        #pragma unroll
        for (int mf = 0; mf < 4; ++mf)
            #pragma unroll
            for (int nf = 0; nf < 2; ++nf) {
                int row = warp_m0 + mf * 16 + g;
                int col = warp_n0 + nf * 8 + t2;
                *(float2*)&Dst[row * 66 + col]       = make_float2(acc[mf][nf][0], acc[mf][nf][1]);
                *(float2*)&Dst[(row + 8) * 66 + col] = make_float2(acc[mf][nf][2], acc[mf][nf][3]);
            }
    }
    __syncthreads();
    #pragma unroll
    for (int it = 0; it < 16; ++it) {
        int qr = wid * 16 + it;
        float2 o = *(const float2*)(Dst + qr * 66 + lane * 2);
        *(float2*)(O + ((size_t)(bh * Qlen + q0 + qr)) * Dd + lane * 2) = o;
    }
}

// ---------------- launch (single stream) ----------------
extern "C" void kernel_launch(void* const* d_in, const int* in_sizes, int n_in,
                              void* d_out, int out_size)
{
    const float*         q     = (const float*)d_in[0];
    const float*         k     = (const float*)d_in[1];
    const float*         v     = (const float*)d_in[2];
    const float*         scale = (const float*)d_in[3];
    const float*         prev  = (const float*)d_in[4];
    const float*         mask  = (const float*)d_in[5];
    const unsigned char* kpm   = (const unsigned char*)d_in[6];

    float* out    = (float*)d_out;
    float* attn   = out  + (size_t)BHn * Qlen * Dd;
    float* scores = attn + (size_t)BHn * QS;

    static int inited = 0;
    if (!inited) {
        cudaFuncSetAttribute(k1_scores, cudaFuncAttributeMaxDynamicSharedMemorySize, K1_SMEM);
        cudaFuncSetAttribute(k3_out,    cudaFuncAttributeMaxDynamicSharedMemorySize, K3_SMEM);
        inited = 1;
    }

    k0_all<<<6144, 256>>>(q, k, v);
    k1_scores<<<dim3(Slen / 128, Qlen / 64, BHn), 256, K1_SMEM>>>(prev, mask, kpm, scale, scores, attn);
    k3_out<<<dim3(Qlen / 128, BHn), 256, K3_SMEM>>>(scores, attn, out);
}

// round 17
// speedup vs baseline: 1.1189x; 1.0013x over previous
#include <cuda_runtime.h>
#include <cuda_bf16.h>
#include <stdint.h>

#define Qlen 2048
#define Slen 2048
#define Dd   64
#define BHn  32
#define NT   16
#define QS   (Qlen * Slen)
#define NROWS (BHn * Qlen)

// ---------------- device scratch (static, allowed) ----------------
__device__ __align__(16) __nv_bfloat16 g_qh[(size_t)BHn * Qlen * Dd];
__device__ __align__(16) __nv_bfloat16 g_ql[(size_t)BHn * Qlen * Dd];
__device__ __align__(16) __nv_bfloat16 g_kth[(size_t)BHn * Slen * Dd];  // k^T: [bh][s][d]
__device__ __align__(16) __nv_bfloat16 g_ktl[(size_t)BHn * Slen * Dd];
__device__ __align__(16) __nv_bfloat16 g_vth[(size_t)BHn * Dd * Slen];  // v^T: [bh][d][s]
__device__ __align__(16) __nv_bfloat16 g_vtl[(size_t)BHn * Dd * Slen];
__device__ float g_partial[(size_t)NROWS * NT];

// ---------------- warp MMA helpers (baseline PTX, sm_80+) ----------------
__device__ __forceinline__ uint32_t smem_u32(const void* p) {
    uint32_t a;
    asm("{ .reg .u64 t; cvta.to.shared.u64 t, %1; cvt.u32.u64 %0, t; }" : "=r"(a) : "l"(p));
    return a;
}
__device__ __forceinline__ void ldsm4(uint32_t (&r)[4], uint32_t addr) {
    asm volatile("ldmatrix.sync.aligned.m8n8.x4.shared.b16 {%0,%1,%2,%3}, [%4];"
        : "=r"(r[0]), "=r"(r[1]), "=r"(r[2]), "=r"(r[3]) : "r"(addr));
}
__device__ __forceinline__ void mma_bf16(float (&d)[4], const uint32_t (&a)[4],
                                         uint32_t b0, uint32_t b1) {
    asm volatile("mma.sync.aligned.m16n8k16.row.col.f32.bf16.bf16.f32 "
        "{%0,%1,%2,%3}, {%4,%5,%6,%7}, {%8,%9}, {%0,%1,%2,%3};"
        : "+f"(d[0]), "+f"(d[1]), "+f"(d[2]), "+f"(d[3])
        : "r"(a[0]), "r"(a[1]), "r"(a[2]), "r"(a[3]), "r"(b0), "r"(b1));
}
__device__ __forceinline__ void split4(float4 x, uint2& hi, uint2& lo) {
    __nv_bfloat16 h0 = __float2bfloat16_rn(x.x), h1 = __float2bfloat16_rn(x.y);
    __nv_bfloat16 h2 = __float2bfloat16_rn(x.z), h3 = __float2bfloat16_rn(x.w);
    float r0 = x.x - __bfloat162float(h0), r1 = x.y - __bfloat162float(h1);
    float r2 = x.z - __bfloat162float(h2), r3 = x.w - __bfloat162float(h3);
    __nv_bfloat162 a = {h0, h1}, b = {h2, h3};
    __nv_bfloat162 c = {__float2bfloat16_rn(r0), __float2bfloat16_rn(r1)};
    __nv_bfloat162 d = {__float2bfloat16_rn(r2), __float2bfloat16_rn(r3)};
    hi.x = *(uint32_t*)&a;  hi.y = *(uint32_t*)&b;
    lo.x = *(uint32_t*)&c;  lo.y = *(uint32_t*)&d;
}

#define SPB 144   // smem row stride in bytes for bf16 tiles (64 elems + 8 pad)
#define NINF __int_as_float(0xff800000)
#define NEG9 (-1.0e9f)

// ---------------- k0: all conversions / transposes in ONE launch ------------
// grid: [0,4096)   -> q split (streaming)
//       [4096,5120)-> k transpose: idx = x-4096, sc = idx & 31, bh = idx >> 5
//       [5120,6144)-> v transpose: idx = x-5120, sc = idx & 31, bh = idx >> 5
__global__ __launch_bounds__(256) void k0_all(
    const float* __restrict__ Q, const float* __restrict__ K,
    const float* __restrict__ V)
{
    __shared__ float T[64][65];
    const int tid = threadIdx.x;
    const int bx = blockIdx.x;

    if (bx < 4096) {                               // ---- q conversion ----
        int j = bx * 256 + tid;
        float4 x = ((const float4*)Q)[j];
        uint2 hi, lo; split4(x, hi, lo);
        ((uint2*)g_qh)[j] = hi;  ((uint2*)g_ql)[j] = lo;
        return;
    }

    const int r = tid >> 4, c4 = tid & 15;
    if (bx < 5120) {                               // ---- k transpose ----
        const int idx = bx - 4096, sc = idx & 31, bh = idx >> 5;
        const int s0 = sc * 64;
        #pragma unroll
        for (int i = 0; i < 4; ++i) {
            int d = r + i * 16;
            float4 x = *(const float4*)(K + ((size_t)(bh * Dd + d)) * Slen + s0 + c4 * 4);
            T[d][c4 * 4] = x.x; T[d][c4 * 4 + 1] = x.y; T[d][c4 * 4 + 2] = x.z; T[d][c4 * 4 + 3] = x.w;
        }
        __syncthreads();
        #pragma unroll
        for (int i = 0; i < 4; ++i) {
            int s = r + i * 16;
            float4 x = make_float4(T[c4 * 4][s], T[c4 * 4 + 1][s], T[c4 * 4 + 2][s], T[c4 * 4 + 3][s]);
            uint2 hi, lo; split4(x, hi, lo);
            size_t off = ((size_t)(bh * Slen + s0 + s)) * Dd + c4 * 4;
            ((uint2*)g_kth)[off >> 2] = hi;  ((uint2*)g_ktl)[off >> 2] = lo;
        }
    } else {                                       // ---- v transpose ----
        const int idx = bx - 5120, sc = idx & 31, bh = idx >> 5;
        const int s0 = sc * 64;
        #pragma unroll
        for (int i = 0; i < 4; ++i) {
            int s = r + i * 16;
            float4 x = *(const float4*)(V + ((size_t)(bh * Slen + s0 + s)) * Dd + c4 * 4);
            T[s][c4 * 4] = x.x; T[s][c4 * 4 + 1] = x.y; T[s][c4 * 4 + 2] = x.z; T[s][c4 * 4 + 3] = x.w;
        }
        __syncthreads();
        #pragma unroll
        for (int i = 0; i < 4; ++i) {
            int d = r + i * 16;
            float4 x = make_float4(T[c4 * 4][d], T[c4 * 4 + 1][d], T[c4 * 4 + 2][d], T[c4 * 4 + 3][d]);
            uint2 hi, lo; split4(x, hi, lo);
            size_t off = ((size_t)(bh * Dd + d)) * Slen + s0 + c4 * 4;
            ((uint2*)g_vth)[off >> 2] = hi;  ((uint2*)g_vtl)[off >> 2] = lo;
        }
    }
}

// ---------------- k1: 64x128 tile, causal-aware, 3 CTAs/SM ------------------
// Fill tiles also zero the attn output. q processed in DESCENDING order.
// smem bytes: Qh@0 (64x144=9216), Ql@9216, Kh@18432 (128x144=18432), Kl@36864.
// Dst (float, 64 x 132 = 33792 B) aliased at 0 after MMA. Total 55296.
#define K1_SMEM 55296
__global__ __launch_bounds__(256, 3) void k1_scores(
    const float* __restrict__ Pp, const float* __restrict__ Mp,
    const unsigned char* __restrict__ KPM, const float* __restrict__ Sc,
    float* __restrict__ OutS, float* __restrict__ OutA)
{
    extern __shared__ char smem[];
    const uint32_t sb = smem_u32(smem);
    float* Dst = (float*)smem;
    const int tid = threadIdx.x, wid = tid >> 5, lane = tid & 31;
    const int bh = blockIdx.z, q0 = (31 - (int)blockIdx.y) * 64, s0 = blockIdx.x * 128, b = bh >> 4;

    // ---- fully-masked tile (s > q everywhere): scores = -1e9, attn = 0 ----
    if (s0 >= q0 + 64) {
        const float4 neg = make_float4(NEG9, NEG9, NEG9, NEG9);
        const float4 zer = make_float4(0.f, 0.f, 0.f, 0.f);
        const size_t base = (size_t)bh * QS + (size_t)q0 * Slen + s0;
        #pragma unroll
        for (int i = 0; i < 8; ++i) {
            int j = tid + i * 256;               // 2048 float4 = 64 rows x 32
            int row = j >> 5, c = j & 31;
            size_t off = base + (size_t)row * Slen + c * 4;
            __stcs((float4*)(OutS + off), neg);
            __stcs((float4*)(OutA + off), zer);
        }
        if (tid < 64)
            g_partial[((size_t)(bh * Qlen + q0 + tid)) * NT + blockIdx.x] = 0.f;
        return;
    }
    const bool needMask = (s0 + 127 > q0);       // any masked element in tile?
    const float scale = *Sc;

    // stage operands: Q 64 rows, K 128 rows (each 128B/row at stride 144B)
    {
        const uint4* qh = (const uint4*)(g_qh + ((size_t)(bh * Qlen + q0)) * Dd);
        const uint4* ql = (const uint4*)(g_ql + ((size_t)(bh * Qlen + q0)) * Dd);
        #pragma unroll
        for (int i = 0; i < 2; ++i) {
            int j = tid + i * 256;
            int r = j >> 3, c = j & 7;
            uint32_t so = r * SPB + c * 16;
            *(uint4*)(smem + so)        = qh[j];
            *(uint4*)(smem + 9216 + so) = ql[j];
        }
        const uint4* kh = (const uint4*)(g_kth + ((size_t)(bh * Slen + s0)) * Dd);
        const uint4* kl = (const uint4*)(g_ktl + ((size_t)(bh * Slen + s0)) * Dd);
        #pragma unroll
        for (int i = 0; i < 4; ++i) {
            int j = tid + i * 256;
            int r = j >> 3, c = j & 7;
            uint32_t so = r * SPB + c * 16;
            *(uint4*)(smem + 18432 + so) = kh[j];
            *(uint4*)(smem + 36864 + so) = kl[j];
        }
    }
    __syncthreads();

    const int warp_m0 = (wid & 3) * 16;
    const int warp_n0 = (wid >> 2) * 64;
    const int quad = lane >> 3, rq = lane & 7;
    const int a_row = ((quad & 1) << 3) + rq;
    const int a_colb = ((quad >> 1) << 4);
    const int b_nfl = quad >> 1;
    const int b_kofb = ((quad & 1) << 4);

    float acc[8][4] = {};
    #pragma unroll
    for (int ks = 0; ks < 4; ++ks) {
        uint32_t ah[4], al[4];
        {
            uint32_t off = (uint32_t)(warp_m0 + a_row) * SPB + ks * 32 + a_colb;
            ldsm4(ah, sb + off);
            ldsm4(al, sb + 9216 + off);
        }
        #pragma unroll
        for (int p = 0; p < 4; ++p) {
            uint32_t off = (uint32_t)(warp_n0 + (p * 2 + b_nfl) * 8 + rq) * SPB + ks * 32 + b_kofb;
            uint32_t th[4], tl[4];
            ldsm4(th, sb + 18432 + off);
            ldsm4(tl, sb + 36864 + off);
            mma_bf16(acc[p * 2],     ah, th[0], th[1]);
            mma_bf16(acc[p * 2],     al, th[0], th[1]);
            mma_bf16(acc[p * 2],     ah, tl[0], tl[1]);
            mma_bf16(acc[p * 2 + 1], ah, th[2], th[3]);
            mma_bf16(acc[p * 2 + 1], al, th[2], th[3]);
            mma_bf16(acc[p * 2 + 1], ah, tl[2], tl[3]);
        }
    }
    __syncthreads();   // operands dead; alias Dst over them

    // acc -> smem stage (stride 132 floats => float4-aligned reads)
    {
        const int g = lane >> 2, t2 = (lane & 3) * 2;
        #pragma unroll
        for (int nf = 0; nf < 8; ++nf) {
            int row = warp_m0 + g;
            int col = warp_n0 + nf * 8 + t2;
            *(float2*)&Dst[row * 132 + col]       = make_float2(acc[nf][0], acc[nf][1]);
            *(float2*)&Dst[(row + 8) * 132 + col] = make_float2(acc[nf][2], acc[nf][3]);
        }
    }
    __syncthreads();

    // epilogue: 8 rows per warp in 2 batches of 4; batched loads for MLP
    {
        const uchar4 kp = *(const uchar4*)(KPM + b * Slen + s0 + lane * 4);
        #pragma unroll
        for (int half = 0; half < 2; ++half) {
            float4 pv[4], mv[4];
            #pragma unroll
            for (int it = 0; it < 4; ++it) {
                int qg = q0 + wid * 8 + half * 4 + it;
                pv[it] = __ldcs((const float4*)(Pp + (size_t)bh * QS + (size_t)qg * Slen + s0 + lane * 4));
                if (needMask)
                    mv[it] = *(const float4*)(Mp + (size_t)qg * Slen + s0 + lane * 4);
                else
                    mv[it] = make_float4(0.f, 0.f, 0.f, 0.f);
            }
            #pragma unroll
            for (int it = 0; it < 4; ++it) {
                int qr = wid * 8 + half * 4 + it, qg = q0 + qr;
                float4 dv = *(const float4*)(Dst + qr * 132 + lane * 4);
                float4 r;
                r.x = fmaf(dv.x, scale, pv[it].x) + mv[it].x;
                r.y = fmaf(dv.y, scale, pv[it].y) + mv[it].y;
                r.z = fmaf(dv.z, scale, pv[it].z) + mv[it].z;
                r.w = fmaf(dv.w, scale, pv[it].w) + mv[it].w;
                if (kp.x) r.x = NINF;
                if (kp.y) r.y = NINF;
                if (kp.z) r.z = NINF;
                if (kp.w) r.w = NINF;
                __stcs((float4*)(OutS + (size_t)bh * QS + (size_t)qg * Slen + s0 + lane * 4), r);
                float e = __expf(r.x) + __expf(r.y) + __expf(r.z) + __expf(r.w);
                #pragma unroll
                for (int o = 16; o; o >>= 1) e += __shfl_xor_sync(0xffffffffu, e, o);
                if (lane == 0) g_partial[((size_t)(bh * Qlen + qg)) * NT + blockIdx.x] = e;
            }
        }
    }
}

// ---------------- k3: causal-aware attn write + out = attn @ v --------------
// Single-buffer inner loop with register prefetch; rowsum reduce inlined.
// smem bytes: Ah@0 (128x144), Al@18432, Bh@36864 (64x144), Bl@46080, inv@55296.
// Dst (float, 128 x 66) aliased at 0 for the final epilogue. Total 55808.
#define K3_SMEM 55808
__global__ __launch_bounds__(256, 2) void k3_out(
    const float* __restrict__ S, float* __restrict__ A, float* __restrict__ O)
{
    extern __shared__ char smem[];
    const uint32_t sb = smem_u32(smem);
    float* smInv = (float*)(smem + 55296);
    float* Dst = (float*)smem;
    const int tid = threadIdx.x, wid = tid >> 5, lane = tid & 31;
    const int qb = 15 - (int)blockIdx.x;                 // descending q order
    const int bh = blockIdx.y, q0 = qb * 128;
    const int cmax = min(32, 2 * qb + 2);                // chunks with any s <= q

    // inline rowsum reduce (k2 eliminated)
    if (tid < 128) {
        const float4* p = (const float4*)(g_partial + (size_t)(bh * Qlen + q0 + tid) * NT);
        float4 a = p[0], b = p[1], c = p[2], d = p[3];
        float s = a.x + a.y + a.z + a.w + b.x + b.y + b.z + b.w
                + c.x + c.y + c.z + c.w + d.x + d.y + d.z + d.w;
        smInv[tid] = 1.0f / s;
    }
    __syncthreads();

    const size_t sbase = (size_t)bh * QS + (size_t)q0 * Slen;
    const uint4* vh = (const uint4*)(g_vth + (size_t)bh * Dd * Slen);
    const uint4* vl = (const uint4*)(g_vtl + (size_t)bh * Dd * Slen);

    const int warp_m0 = (wid & 1) * 64;
    const int warp_n0 = (wid >> 1) * 16;
    const int quad = lane >> 3, rq = lane & 7;
    const int a_row = ((quad & 1) << 3) + rq;
    const int a_colb = ((quad >> 1) << 4);
    const int b_nfl = quad >> 1;
    const int b_kofb = ((quad & 1) << 4);

    const int sqr = tid >> 4, sf4 = tid & 15;
    const int vd  = tid >> 3, vc8 = tid & 7;

    float acc[4][2][4] = {};
    float4 xr[8];
    uint4  vb[2][2];

    #pragma unroll
    for (int i = 0; i < 8; ++i)
        xr[i] = __ldcs((const float4*)(S + sbase + (size_t)(sqr + i * 16) * Slen + sf4 * 4));
    #pragma unroll
    for (int i = 0; i < 2; ++i) {
        size_t eidx = (((size_t)(vd + i * 32) * Slen) >> 3) + vc8;
        vb[i][0] = vh[eidx];  vb[i][1] = vl[eidx];
    }

    for (int c = 0; c < cmax; ++c) {
        #pragma unroll
        for (int i = 0; i < 8; ++i) {
            int qr = sqr + i * 16;
            float iv = smInv[qr];
            float4 p;
            p.x = __expf(xr[i].x) * iv;  p.y = __expf(xr[i].y) * iv;
            p.z = __expf(xr[i].z) * iv;  p.w = __expf(xr[i].w) * iv;
            __stcs((float4*)(A + sbase + (size_t)qr * Slen + c * 64 + sf4 * 4), p);
            uint2 hi, lo; split4(p, hi, lo);
            uint32_t so = (uint32_t)qr * SPB + sf4 * 8;
            *(uint2*)(smem + so)         = hi;
            *(uint2*)(smem + 18432 + so) = lo;
        }
        #pragma unroll
        for (int i = 0; i < 2; ++i) {
            uint32_t so = (uint32_t)(vd + i * 32) * SPB + vc8 * 16;
            *(uint4*)(smem + 36864 + so) = vb[i][0];
            *(uint4*)(smem + 46080 + so) = vb[i][1];
        }
        __syncthreads();

        if (c + 1 < cmax) {
            #pragma unroll
            for (int i = 0; i < 8; ++i)
                xr[i] = __ldcs((const float4*)(S + sbase + (size_t)(sqr + i * 16) * Slen + (c + 1) * 64 + sf4 * 4));
            #pragma unroll
            for (int i = 0; i < 2; ++i) {
                size_t eidx = (((size_t)(vd + i * 32) * Slen + (c + 1) * 64) >> 3) + vc8;
                vb[i][0] = vh[eidx];  vb[i][1] = vl[eidx];
            }
        }

        #pragma unroll
        for (int ks = 0; ks < 4; ++ks) {
            uint32_t bhf[4], blf[4];
            {
                uint32_t off = (uint32_t)(warp_n0 + b_nfl * 8 + rq) * SPB + ks * 32 + b_kofb;
                ldsm4(bhf, sb + 36864 + off);
                ldsm4(blf, sb + 46080 + off);
            }
            #pragma unroll
            for (int mf = 0; mf < 4; ++mf) {
                uint32_t ah[4], al[4];
                uint32_t off = (uint32_t)(warp_m0 + mf * 16 + a_row) * SPB + ks * 32 + a_colb;
                ldsm4(ah, sb + off);
                ldsm4(al, sb + 18432 + off);
                mma_bf16(acc[mf][0], ah, bhf[0], bhf[1]);
                mma_bf16(acc[mf][0], al, bhf[0], bhf[1]);
                mma_bf16(acc[mf][0], ah, blf[0], blf[1]);
                mma_bf16(acc[mf][1], ah, bhf[2], bhf[3]);
                mma_bf16(acc[mf][1], al, bhf[2], bhf[3]);
                mma_bf16(acc[mf][1], ah, blf[2], blf[3]);
            }
        }
        __syncthreads();
    }

    {
        const int g = lane >> 2, t2 = (lane & 3) * 2;
        #pragma unroll
        for (int mf = 0; mf < 4; ++mf)
            #pragma unroll
            for (int nf = 0; nf < 2; ++nf) {
                int row = warp_m0 + mf * 16 + g;
                int col = warp_n0 + nf * 8 + t2;
                *(float2*)&Dst[row * 66 + col]       = make_float2(acc[mf][nf][0], acc[mf][nf][1]);
                *(float2*)&Dst[(row + 8) * 66 + col] = make_float2(acc[mf][nf][2], acc[mf][nf][3]);
            }
    }
    __syncthreads();
    #pragma unroll
    for (int it = 0; it < 16; ++it) {
        int qr = wid * 16 + it;
        float2 o = *(const float2*)(Dst + qr * 66 + lane * 2);
        *(float2*)(O + ((size_t)(bh * Qlen + q0 + qr)) * Dd + lane * 2) = o;
    }
}

// ---------------- launch (single stream) ----------------
extern "C" void kernel_launch(void* const* d_in, const int* in_sizes, int n_in,
                              void* d_out, int out_size)
{
    const float*         q     = (const float*)d_in[0];
    const float*         k     = (const float*)d_in[1];
    const float*         v     = (const float*)d_in[2];
    const float*         scale = (const float*)d_in[3];
    const float*         prev  = (const float*)d_in[4];
    const float*         mask  = (const float*)d_in[5];
    const unsigned char* kpm   = (const unsigned char*)d_in[6];

    float* out    = (float*)d_out;
    float* attn   = out  + (size_t)BHn * Qlen * Dd;
    float* scores = attn + (size_t)BHn * QS;

    static int inited = 0;
    if (!inited) {
        cudaFuncSetAttribute(k1_scores, cudaFuncAttributeMaxDynamicSharedMemorySize, K1_SMEM);
        cudaFuncSetAttribute(k3_out,    cudaFuncAttributeMaxDynamicSharedMemorySize, K3_SMEM);
        inited = 1;
    }

    k0_all<<<6144, 256>>>(q, k, v);
    k1_scores<<<dim3(Slen / 128, Qlen / 64, BHn), 256, K1_SMEM>>>(prev, mask, kpm, scale, scores, attn);
    k3_out<<<dim3(Qlen / 128, BHn), 256, K3_SMEM>>>(scores, attn, out);
}